// round 8
// baseline (speedup 1.0000x reference)
#include <cuda_runtime.h>
#include <cstdint>
#include <cstddef>

#define TT   512
#define BB   128
#define EE   512
#define HH   512
#define G5   2560
#define LEE  512
#define EPSV 1e-5f
#define NBLK 128      // LSTM persistent blocks
#define CK   64       // LSTM k-chunk

// ------------------------- static device scratch ---------------------------
__device__ float    g_pre[(size_t)TT * BB * G5];   // [t*128+b][2560]
__device__ float    g_hbuf[3][BB * HH];            // rotating hidden buffers
__device__ float    g_xsel[BB * HH];               // outs[label_len[b], b]
__device__ float    g_z0[BB * LEE];
__device__ unsigned g_sync;

// ------------------- packed f32x2 FMA (sm_103a FFMA2) ----------------------
union F2U { float2 f; unsigned long long u; };
__device__ __forceinline__ void ffma2(F2U& acc, F2U a, F2U b) {
    asm("fma.rn.f32x2 %0, %1, %2, %0;" : "+l"(acc.u) : "l"(a.u), "l"(b.u));
}
__device__ __forceinline__ float sgm(float x) { return 1.f / (1.f + __expf(-x)); }

// ------------------------------- init --------------------------------------
__global__ void k_init() {
    int i = blockIdx.x * blockDim.x + threadIdx.x;
    if (i < BB * HH) g_hbuf[0][i] = 0.f;
    if (i == 0) g_sync = 0u;
}

// ---------------- K1: pre = gather(embed) @ i2h_w^T + i2h_b ----------------
// M = T*B (m = t*128+b), N = 2560, K = 512. BM=BN=128, BK=8, 256 thr, 8x8/thr.
__global__ __launch_bounds__(256, 2)
void k_pre(const int* __restrict__ label, const float* __restrict__ embed_w,
           const float* __restrict__ i2h_w, const float* __restrict__ i2h_b)
{
    __shared__ __align__(16) float As[8][128];
    __shared__ __align__(16) float Ws[8][128];

    const int tid = threadIdx.x;
    const int tx = tid & 15, ty = tid >> 4;
    const int n0 = blockIdx.x * 128, m0 = blockIdx.y * 128;
    const int ml = tid >> 1, lk = (tid & 1) * 4;

    const int m = m0 + ml, t_ = m >> 7, b_ = m & 127;
    const float* arow = embed_w + (size_t)label[b_ * TT + t_] * EE;
    const float* wrow = i2h_w + (size_t)(n0 + ml) * EE;

    F2U acc[8][4];
    #pragma unroll
    for (int i = 0; i < 8; i++)
        #pragma unroll
        for (int j = 0; j < 4; j++) acc[i][j].u = 0ull;

    float4 ra = *(const float4*)(arow + lk);
    float4 rw = *(const float4*)(wrow + lk);

    #pragma unroll 1
    for (int ko = 0; ko < EE / 8; ++ko) {
        __syncthreads();
        As[lk + 0][ml] = ra.x; As[lk + 1][ml] = ra.y;
        As[lk + 2][ml] = ra.z; As[lk + 3][ml] = ra.w;
        Ws[lk + 0][ml] = rw.x; Ws[lk + 1][ml] = rw.y;
        Ws[lk + 2][ml] = rw.z; Ws[lk + 3][ml] = rw.w;
        __syncthreads();
        if (ko + 1 < EE / 8) {
            int kb = (ko + 1) * 8 + lk;
            ra = *(const float4*)(arow + kb);
            rw = *(const float4*)(wrow + kb);
        }
        #pragma unroll
        for (int k = 0; k < 8; ++k) {
            float4 aA = *(const float4*)&As[k][ty * 8];
            float4 aB = *(const float4*)&As[k][ty * 8 + 4];
            float4 bA = *(const float4*)&Ws[k][tx * 8];
            float4 bB = *(const float4*)&Ws[k][tx * 8 + 4];
            float av[8] = {aA.x, aA.y, aA.z, aA.w, aB.x, aB.y, aB.z, aB.w};
            F2U bp[4];
            bp[0].f = make_float2(bA.x, bA.y);
            bp[1].f = make_float2(bA.z, bA.w);
            bp[2].f = make_float2(bB.x, bB.y);
            bp[3].f = make_float2(bB.z, bB.w);
            #pragma unroll
            for (int i = 0; i < 8; i++) {
                F2U ad; ad.f.x = av[i]; ad.f.y = av[i];
                #pragma unroll
                for (int j = 0; j < 4; j++) ffma2(acc[i][j], ad, bp[j]);
            }
        }
    }

    const float4 bi0 = *(const float4*)(i2h_b + n0 + tx * 8);
    const float4 bi1 = *(const float4*)(i2h_b + n0 + tx * 8 + 4);
    #pragma unroll
    for (int i = 0; i < 8; i++) {
        const int mrow = m0 + ty * 8 + i;
        float* op = g_pre + (size_t)mrow * G5 + n0 + tx * 8;
        float4 o0, o1;
        o0.x = acc[i][0].f.x + bi0.x; o0.y = acc[i][0].f.y + bi0.y;
        o0.z = acc[i][1].f.x + bi0.z; o0.w = acc[i][1].f.y + bi0.w;
        o1.x = acc[i][2].f.x + bi1.x; o1.y = acc[i][2].f.y + bi1.y;
        o1.z = acc[i][3].f.x + bi1.z; o1.w = acc[i][3].f.y + bi1.w;
        *(float4*)op = o0;
        *(float4*)(op + 4) = o1;
    }
}

// ------------------------- K2: persistent LSTM -----------------------------
// 128 blocks x 256 threads. Block owns 4 hidden units (ju = blk*4 + jj).
// Thread (jj = tid>>6, bp = tid&63) computes all 5 gates for b = bp, bp+64.
// Cell state in registers across all 512 steps. Grid barrier per step.
__global__ __launch_bounds__(256, 1)
void k_lstm(const float* __restrict__ h2h_w, const float* __restrict__ h2h_b,
            const int* __restrict__ llen)
{
    extern __shared__ float sm[];
    float* w_s = sm;                 // [20][512]  rows r = g*4 + u
    float* h_s = sm + 20 * HH;       // [CK][128]  k-major chunk

    const int tid = threadIdx.x;
    const int jj  = tid >> 6;
    const int bp  = tid & 63;
    const int b0  = bp, b1 = bp + 64;
    const int blk = blockIdx.x;
    const int ju  = blk * 4 + jj;

    // resident weights: 20 rows x 512 = 2560 float4s / 256 thr = 10 each
    for (int i = tid; i < 20 * HH / 4; i += 256) {
        int r = i / (HH / 4), k4 = i % (HH / 4);
        int g = r >> 2, u = r & 3;
        *(float4*)(w_s + r * HH + k4 * 4) =
            *(const float4*)(h2h_w + (size_t)(g * HH + blk * 4 + u) * HH + k4 * 4);
    }

    float bias[5];
    #pragma unroll
    for (int g = 0; g < 5; g++) bias[g] = h2h_b[g * HH + ju];
    const int L0 = llen[b0], L1 = llen[b1];

    float c0 = 0.f, c1 = 0.f;
    const int lb = tid >> 1, lh = tid & 1;   // staging loader mapping

    __syncthreads();

    #pragma unroll 1
    for (int t = 0; t < TT; ++t) {
        const float* hcur = g_hbuf[t % 3];
        float*       hnxt = g_hbuf[(t + 1) % 3];

        F2U acc0[5], acc1[5];
        #pragma unroll
        for (int g = 0; g < 5; g++) { acc0[g].u = 0ull; acc1[g].u = 0ull; }

        float pv0[5], pv1[5];
        #pragma unroll
        for (int g = 0; g < 5; g++) {
            pv0[g] = __ldg(&g_pre[((size_t)t * BB + b0) * G5 + g * HH + ju]);
            pv1[g] = __ldg(&g_pre[((size_t)t * BB + b1) * G5 + g * HH + ju]);
        }

        // prefetch chunk 0 (L2-coherent: peers' writes bypass our stale L1)
        float4 rg[8];
        {
            const float* src = hcur + lb * HH + lh * 32;
            #pragma unroll
            for (int q = 0; q < 8; q++) rg[q] = __ldcg((const float4*)(src + q * 4));
        }

        #pragma unroll 1
        for (int ch = 0; ch < HH / CK; ++ch) {
            __syncthreads();
            #pragma unroll
            for (int q = 0; q < 8; q++) {
                int kk = lh * 32 + q * 4;
                h_s[(kk + 0) * BB + lb] = rg[q].x;
                h_s[(kk + 1) * BB + lb] = rg[q].y;
                h_s[(kk + 2) * BB + lb] = rg[q].z;
                h_s[(kk + 3) * BB + lb] = rg[q].w;
            }
            __syncthreads();
            if (ch + 1 < HH / CK) {
                const float* src = hcur + lb * HH + (ch + 1) * CK + lh * 32;
                #pragma unroll
                for (int q = 0; q < 8; q++) rg[q] = __ldcg((const float4*)(src + q * 4));
            }
            const float* wb = w_s + ch * CK;
            #pragma unroll
            for (int kq = 0; kq < CK / 4; ++kq) {
                const int kb = kq * 4;
                F2U h0a, h0b, h1a, h1b;
                h0a.f.x = h_s[(kb + 0) * BB + b0]; h0a.f.y = h_s[(kb + 1) * BB + b0];
                h0b.f.x = h_s[(kb + 2) * BB + b0]; h0b.f.y = h_s[(kb + 3) * BB + b0];
                h1a.f.x = h_s[(kb + 0) * BB + b1]; h1a.f.y = h_s[(kb + 1) * BB + b1];
                h1b.f.x = h_s[(kb + 2) * BB + b1]; h1b.f.y = h_s[(kb + 3) * BB + b1];
                #pragma unroll
                for (int g = 0; g < 5; g++) {
                    float4 wv = *(const float4*)(wb + (g * 4 + jj) * HH + kb);
                    F2U wa, wc;
                    wa.f = make_float2(wv.x, wv.y);
                    wc.f = make_float2(wv.z, wv.w);
                    ffma2(acc0[g], h0a, wa); ffma2(acc0[g], h0b, wc);
                    ffma2(acc1[g], h1a, wa); ffma2(acc1[g], h1b, wc);
                }
            }
        }

        // nonlinearity + state update (cell state never leaves registers)
        {
            float s0[5], s1[5];
            #pragma unroll
            for (int g = 0; g < 5; g++) {
                s0[g] = acc0[g].f.x + acc0[g].f.y + bias[g] + pv0[g];
                s1[g] = acc1[g].f.x + acc1[g].f.y + bias[g] + pv1[g];
            }
            float i0 = sgm(s0[0]), f0 = sgm(s0[1]), o0 = sgm(s0[2]);
            float i1 = sgm(s1[0]), f1 = sgm(s1[1]), o1 = sgm(s1[2]);
            float a0 = fmaxf(s0[3], s0[4]), a1 = fmaxf(s1[3], s1[4]);
            c0 = f0 * c0 + i0 * a0;
            c1 = f1 * c1 + i1 * a1;
            float nh0 = o0 * tanhf(c0);
            float nh1 = o1 * tanhf(c1);
            hnxt[b0 * HH + ju] = nh0;
            hnxt[b1 * HH + ju] = nh1;
            if (t == L0) g_xsel[b0 * HH + ju] = nh0;
            if (t == L1) g_xsel[b1 * HH + ju] = nh1;
        }

        // grid barrier (128 co-resident blocks; counter monotone per step)
        __syncthreads();
        if (tid == 0) {
            __threadfence();
            atomicAdd(&g_sync, 1u);
            const unsigned tgt = (unsigned)(t + 1) * NBLK;
            while (*(volatile unsigned*)&g_sync < tgt) { }
            __threadfence();
        }
        __syncthreads();
    }
}

// ---------------- K3: linear + batchnorm (+relu), one block per column -----
__global__ __launch_bounds__(128, 8)
void k_head(const float* __restrict__ w, const float* __restrict__ bias,
            const float* __restrict__ gam, const float* __restrict__ bet,
            float* __restrict__ dout, int phase)
{
    __shared__ float w_s[LEE];
    __shared__ float red[BB];
    const int n = blockIdx.x, b = threadIdx.x;
    const float* x   = phase ? g_z0 : g_xsel;
    float*       out = phase ? dout : g_z0;

    for (int k = b; k < LEE; k += BB) w_s[k] = w[(size_t)n * LEE + k];
    __syncthreads();

    float s = 0.f;
    const float* xr = x + (size_t)b * LEE;
    #pragma unroll 4
    for (int k = 0; k < LEE; k += 4) {
        float4 xv = *(const float4*)(xr + k);
        float4 wv = *(const float4*)(w_s + k);
        s += xv.x * wv.x + xv.y * wv.y + xv.z * wv.z + xv.w * wv.w;
    }
    s += bias[n];

    red[b] = s; __syncthreads();
    #pragma unroll
    for (int off = 64; off > 0; off >>= 1) {
        if (b < off) red[b] += red[b + off];
        __syncthreads();
    }
    const float mean = red[0] * (1.f / BB);
    __syncthreads();
    const float d = s - mean;
    red[b] = d * d; __syncthreads();
    #pragma unroll
    for (int off = 64; off > 0; off >>= 1) {
        if (b < off) red[b] += red[b + off];
        __syncthreads();
    }
    const float var = red[0] * (1.f / BB);

    float y = d * rsqrtf(var + EPSV) * gam[n] + bet[n];
    if (!phase) y = fmaxf(y, 0.f);
    out[(size_t)b * LEE + n] = y;
}

// ------------------------------ launcher -----------------------------------
extern "C" void kernel_launch(void* const* d_in, const int* in_sizes, int n_in,
                              void* d_out, int out_size)
{
    const int*   label    = (const int*)  d_in[0];
    const int*   llen     = (const int*)  d_in[1];
    const float* embed_w  = (const float*)d_in[2];
    const float* i2h_w    = (const float*)d_in[3];
    const float* i2h_b    = (const float*)d_in[4];
    const float* h2h_w    = (const float*)d_in[5];
    const float* h2h_b    = (const float*)d_in[6];
    const float* lin0_w   = (const float*)d_in[7];
    const float* lin0_b   = (const float*)d_in[8];
    const float* bn0_g    = (const float*)d_in[9];
    const float* bn0_b    = (const float*)d_in[10];
    const float* lin1_w   = (const float*)d_in[11];
    const float* lin1_b   = (const float*)d_in[12];
    const float* bn1_g    = (const float*)d_in[13];
    const float* bn1_b    = (const float*)d_in[14];
    float*       out      = (float*)d_out;

    const int smem_lstm = (20 * HH + CK * BB) * (int)sizeof(float);  // 72 KB
    static int attr_done = 0;
    if (!attr_done) {
        cudaFuncSetAttribute(k_lstm, cudaFuncAttributeMaxDynamicSharedMemorySize,
                             smem_lstm);
        attr_done = 1;
    }

    k_init<<<256, 256>>>();
    k_pre<<<dim3(G5 / 128, (TT * BB) / 128), 256>>>(label, embed_w, i2h_w, i2h_b);
    k_lstm<<<NBLK, 256, smem_lstm>>>(h2h_w, h2h_b, llen);
    k_head<<<LEE, BB>>>(lin0_w, lin0_b, bn0_g, bn0_b, out, 0);
    k_head<<<LEE, BB>>>(lin1_w, lin1_b, bn1_g, bn1_b, out, 1);
}

// round 9
// speedup vs baseline: 1.3814x; 1.3814x over previous
#include <cuda_runtime.h>
#include <cstdint>
#include <cstddef>

#define TT   512
#define BB   128
#define EE   512
#define HH   512
#define G5   2560
#define LEE  512
#define EPSV 1e-5f
#define NBLK 128      // LSTM persistent blocks
#define CK   64       // LSTM k-chunk

// ------------------------- static device scratch ---------------------------
__device__ float    g_pre[(size_t)TT * BB * G5];   // [t*128+b][2560]
__device__ float    g_hbuf[3][BB * HH];            // rotating hidden (SLOT space)
__device__ float    g_xsel[BB * HH];               // outs[label_len[b], b] (real b)
__device__ float    g_z0[BB * LEE];
__device__ unsigned g_sync;
__device__ int      g_slot2b[BB];                  // slot -> real batch
__device__ int      g_Lslot[BB];                   // slot -> label_len
__device__ int      g_maxL;

// ------------------- packed f32x2 FMA (sm_103a FFMA2) ----------------------
union F2U { float2 f; unsigned long long u; };
struct F4v { F2U lo, hi; };   // 16B = two f32x2 lanes
__device__ __forceinline__ void ffma2(F2U& acc, F2U a, F2U b) {
    asm("fma.rn.f32x2 %0, %1, %2, %0;" : "+l"(acc.u) : "l"(a.u), "l"(b.u));
}
__device__ __forceinline__ float sgm(float x) { return 1.f / (1.f + __expf(-x)); }
__device__ __forceinline__ float tanh_fast(float x) {
    // tanh(x) = 1 - 2/(1+e^{2x})
    return 1.f - 2.f / (1.f + __expf(2.f * x));
}

// --------------------------- init + length sort ----------------------------
__global__ void k_init(const int* __restrict__ llen) {
    int i = blockIdx.x * blockDim.x + threadIdx.x;
    if (i < BB * HH) g_hbuf[0][i] = 0.f;
    if (i == 0) g_sync = 0u;
    if (blockIdx.x == 0 && threadIdx.x < BB) {
        int b  = threadIdx.x;
        int Lb = llen[b];
        int r = 0, mx = 0;
        #pragma unroll 4
        for (int j = 0; j < BB; j++) {
            int Lj = llen[j];
            r  += (Lj < Lb) || (Lj == Lb && j < b);
            mx  = max(mx, Lj);
        }
        int s = (r >> 1) + (r & 1) * 64;   // adjacent ranks -> slot pair (s, s+64)
        g_slot2b[s] = b;
        g_Lslot[s]  = Lb;
        if (b == 0) g_maxL = 0;            // overwritten below by all, same value
        if (threadIdx.x == 0) g_maxL = mx;
    }
}

// ---------------- K1: pre = gather(embed) @ i2h_w^T + i2h_b ----------------
// M = T*B (m = t*128+b), N = 2560, K = 512. BM=BN=128, BK=8, 256 thr, 8x8/thr.
// Per-thread columns: (tx*4 .. +3) and (64+tx*4 .. +3)  -> conflict-free LDS.
__global__ __launch_bounds__(256, 2)
void k_pre(const int* __restrict__ label, const float* __restrict__ embed_w,
           const float* __restrict__ i2h_w, const float* __restrict__ i2h_b)
{
    __shared__ __align__(16) float As[8][128];
    __shared__ __align__(16) float Ws[8][128];

    const int tid = threadIdx.x;
    const int tx = tid & 15, ty = tid >> 4;
    const int n0 = blockIdx.x * 128, m0 = blockIdx.y * 128;
    const int ml = tid >> 1, lk = (tid & 1) * 4;

    const int m = m0 + ml, t_ = m >> 7, b_ = m & 127;
    const float* arow = embed_w + (size_t)label[b_ * TT + t_] * EE;
    const float* wrow = i2h_w + (size_t)(n0 + ml) * EE;

    F2U acc[8][4];
    #pragma unroll
    for (int i = 0; i < 8; i++)
        #pragma unroll
        for (int j = 0; j < 4; j++) acc[i][j].u = 0ull;

    float4 ra = *(const float4*)(arow + lk);
    float4 rw = *(const float4*)(wrow + lk);

    #pragma unroll 1
    for (int ko = 0; ko < EE / 8; ++ko) {
        __syncthreads();
        As[lk + 0][ml] = ra.x; As[lk + 1][ml] = ra.y;
        As[lk + 2][ml] = ra.z; As[lk + 3][ml] = ra.w;
        Ws[lk + 0][ml] = rw.x; Ws[lk + 1][ml] = rw.y;
        Ws[lk + 2][ml] = rw.z; Ws[lk + 3][ml] = rw.w;
        __syncthreads();
        if (ko + 1 < EE / 8) {
            int kb = (ko + 1) * 8 + lk;
            ra = *(const float4*)(arow + kb);
            rw = *(const float4*)(wrow + kb);
        }
        #pragma unroll
        for (int k = 0; k < 8; ++k) {
            float4 aA = *(const float4*)&As[k][ty * 8];       // broadcast
            float4 aB = *(const float4*)&As[k][ty * 8 + 4];   // broadcast
            F4v bA = *(const F4v*)&Ws[k][tx * 4];             // conflict-free
            F4v bB = *(const F4v*)&Ws[k][64 + tx * 4];        // conflict-free
            float av[8] = {aA.x, aA.y, aA.z, aA.w, aB.x, aB.y, aB.z, aB.w};
            #pragma unroll
            for (int i = 0; i < 8; i++) {
                F2U ad; ad.f.x = av[i]; ad.f.y = av[i];
                ffma2(acc[i][0], ad, bA.lo);
                ffma2(acc[i][1], ad, bA.hi);
                ffma2(acc[i][2], ad, bB.lo);
                ffma2(acc[i][3], ad, bB.hi);
            }
        }
    }

    const float4 bi0 = *(const float4*)(i2h_b + n0 + tx * 4);
    const float4 bi1 = *(const float4*)(i2h_b + n0 + 64 + tx * 4);
    #pragma unroll
    for (int i = 0; i < 8; i++) {
        const int mrow = m0 + ty * 8 + i;
        float* op = g_pre + (size_t)mrow * G5 + n0 + tx * 4;
        float4 o0, o1;
        o0.x = acc[i][0].f.x + bi0.x; o0.y = acc[i][0].f.y + bi0.y;
        o0.z = acc[i][1].f.x + bi0.z; o0.w = acc[i][1].f.y + bi0.w;
        o1.x = acc[i][2].f.x + bi1.x; o1.y = acc[i][2].f.y + bi1.y;
        o1.z = acc[i][3].f.x + bi1.z; o1.w = acc[i][3].f.y + bi1.w;
        *(float4*)op        = o0;
        *(float4*)(op + 64) = o1;
    }
}

// ------------------------- K2: persistent LSTM -----------------------------
// 128 blocks x 256 threads. Block owns 4 hidden units (ju = blk*4 + jj).
// Hidden state lives in SLOT space (length-sorted pairs): thread (jj, bp)
// handles slots bp and bp+64 = sorted ranks 2bp, 2bp+1 -> warps retire
// together and skip work once t exceeds their max label_len.
__global__ __launch_bounds__(256, 1)
void k_lstm(const float* __restrict__ h2h_w, const float* __restrict__ h2h_b)
{
    extern __shared__ float sm[];
    float* w_s = sm;                 // [20][512]  rows r = g*4 + u
    float* h_s = sm + 20 * HH;       // [16][128][4]  k4-major chunk (CK=64)

    const int tid = threadIdx.x;
    const int jj  = tid >> 6;
    const int bp  = tid & 63;
    const int s0  = bp, s1 = bp + 64;
    const int blk = blockIdx.x;
    const int ju  = blk * 4 + jj;

    // resident weights: 20 rows x 512
    for (int i = tid; i < 20 * HH / 4; i += 256) {
        int r = i / (HH / 4), k4 = i % (HH / 4);
        int g = r >> 2, u = r & 3;
        *(float4*)(w_s + r * HH + k4 * 4) =
            *(const float4*)(h2h_w + (size_t)(g * HH + blk * 4 + u) * HH + k4 * 4);
    }

    float bias[5];
    #pragma unroll
    for (int g = 0; g < 5; g++) bias[g] = h2h_b[g * HH + ju];

    const int b0 = g_slot2b[s0], b1 = g_slot2b[s1];
    const int L0 = g_Lslot[s0],  L1 = g_Lslot[s1];     // L1 >= L0 by construction
    const int maxT = g_maxL;

    // staging loader mapping: thread stages 32 k of slot row ls
    const int ls = tid & 127, lh = tid >> 7;
    const int Lstage = g_Lslot[(ls & 63) + 64];        // owner-pair max L

    float c0 = 0.f, c1 = 0.f;
    __syncthreads();

    #pragma unroll 1
    for (int t = 0; t <= maxT; ++t) {
        const float* hcur = g_hbuf[t % 3];
        float*       hnxt = g_hbuf[(t + 1) % 3];
        const bool act    = (t <= L1);
        const bool act0   = (t <= L0);
        const bool stg    = (t <= Lstage);

        F2U acc0[5], acc1[5];
        #pragma unroll
        for (int g = 0; g < 5; g++) { acc0[g].u = 0ull; acc1[g].u = 0ull; }

        float pv0[5], pv1[5];
        #pragma unroll
        for (int g = 0; g < 5; g++) { pv0[g] = 0.f; pv1[g] = 0.f; }
        if (act0) {
            #pragma unroll
            for (int g = 0; g < 5; g++)
                pv0[g] = __ldg(&g_pre[((size_t)t * BB + b0) * G5 + g * HH + ju]);
        }
        if (act) {
            #pragma unroll
            for (int g = 0; g < 5; g++)
                pv1[g] = __ldg(&g_pre[((size_t)t * BB + b1) * G5 + g * HH + ju]);
        }

        // prefetch chunk 0 (L2 path: peers' h writes, our L1 may be stale)
        float4 rg[8];
        if (stg) {
            const float* src = hcur + ls * HH + lh * 32;
            #pragma unroll
            for (int q = 0; q < 8; q++) rg[q] = __ldcg((const float4*)(src + q * 4));
        }

        #pragma unroll 1
        for (int ch = 0; ch < HH / CK; ++ch) {
            __syncthreads();
            if (stg) {
                #pragma unroll
                for (int q = 0; q < 8; q++)   // h_s[k4 = lh*8+q][ls][0..3]
                    *(float4*)(h_s + ((lh * 8 + q) * BB + ls) * 4) = rg[q];
            }
            __syncthreads();
            if (stg && ch + 1 < HH / CK) {
                const float* src = hcur + ls * HH + (ch + 1) * CK + lh * 32;
                #pragma unroll
                for (int q = 0; q < 8; q++) rg[q] = __ldcg((const float4*)(src + q * 4));
            }
            if (act) {
                const F4v* hp = (const F4v*)h_s;
                #pragma unroll
                for (int kq = 0; kq < CK / 4; ++kq) {
                    F4v h0 = hp[kq * BB + s0];     // conflict-free
                    F4v h1 = hp[kq * BB + s1];     // conflict-free
                    #pragma unroll
                    for (int g = 0; g < 5; g++) {
                        F4v wv = *(const F4v*)(w_s + (size_t)(g * 4 + jj) * HH
                                               + ch * CK + kq * 4);   // broadcast
                        ffma2(acc0[g], h0.lo, wv.lo); ffma2(acc0[g], h0.hi, wv.hi);
                        ffma2(acc1[g], h1.lo, wv.lo); ffma2(acc1[g], h1.hi, wv.hi);
                    }
                }
            }
        }

        if (act) {
            float s0v[5], s1v[5];
            #pragma unroll
            for (int g = 0; g < 5; g++) {
                s0v[g] = acc0[g].f.x + acc0[g].f.y + bias[g] + pv0[g];
                s1v[g] = acc1[g].f.x + acc1[g].f.y + bias[g] + pv1[g];
            }
            float i1g = sgm(s1v[0]), f1g = sgm(s1v[1]), o1g = sgm(s1v[2]);
            float a1  = fmaxf(s1v[3], s1v[4]);
            c1 = f1g * c1 + i1g * a1;
            float nh1 = o1g * tanh_fast(c1);
            hnxt[s1 * HH + ju] = nh1;
            if (t == L1) g_xsel[b1 * HH + ju] = nh1;

            if (act0) {
                float i0g = sgm(s0v[0]), f0g = sgm(s0v[1]), o0g = sgm(s0v[2]);
                float a0  = fmaxf(s0v[3], s0v[4]);
                c0 = f0g * c0 + i0g * a0;
                float nh0 = o0g * tanh_fast(c0);
                hnxt[s0 * HH + ju] = nh0;
                if (t == L0) g_xsel[b0 * HH + ju] = nh0;
            }
        }

        // grid barrier: release-arrive + acquire-spin (no L1-flush fences)
        __syncthreads();
        if (tid == 0) {
            __threadfence();                       // release our block's h writes
            atomicAdd(&g_sync, 1u);
            const unsigned tgt = (unsigned)(t + 1) * NBLK;
            unsigned v;
            do {
                asm volatile("ld.acquire.gpu.u32 %0, [%1];"
                             : "=r"(v) : "l"(&g_sync));
            } while (v < tgt);
        }
        __syncthreads();
    }
}

// ---------------- K3: linear + batchnorm (+relu), one block per column -----
__global__ __launch_bounds__(128, 8)
void k_head(const float* __restrict__ w, const float* __restrict__ bias,
            const float* __restrict__ gam, const float* __restrict__ bet,
            float* __restrict__ dout, int phase)
{
    __shared__ float w_s[LEE];
    __shared__ float red[BB];
    const int n = blockIdx.x, b = threadIdx.x;
    const float* x   = phase ? g_z0 : g_xsel;
    float*       out = phase ? dout : g_z0;

    for (int k = b; k < LEE; k += BB) w_s[k] = w[(size_t)n * LEE + k];
    __syncthreads();

    float s = 0.f;
    const float* xr = x + (size_t)b * LEE;
    #pragma unroll 4
    for (int k = 0; k < LEE; k += 4) {
        float4 xv = *(const float4*)(xr + k);
        float4 wv = *(const float4*)(w_s + k);
        s += xv.x * wv.x + xv.y * wv.y + xv.z * wv.z + xv.w * wv.w;
    }
    s += bias[n];

    red[b] = s; __syncthreads();
    #pragma unroll
    for (int off = 64; off > 0; off >>= 1) {
        if (b < off) red[b] += red[b + off];
        __syncthreads();
    }
    const float mean = red[0] * (1.f / BB);
    __syncthreads();
    const float d = s - mean;
    red[b] = d * d; __syncthreads();
    #pragma unroll
    for (int off = 64; off > 0; off >>= 1) {
        if (b < off) red[b] += red[b + off];
        __syncthreads();
    }
    const float var = red[0] * (1.f / BB);

    float y = d * rsqrtf(var + EPSV) * gam[n] + bet[n];
    if (!phase) y = fmaxf(y, 0.f);
    out[(size_t)b * LEE + n] = y;
}

// ------------------------------ launcher -----------------------------------
extern "C" void kernel_launch(void* const* d_in, const int* in_sizes, int n_in,
                              void* d_out, int out_size)
{
    const int*   label    = (const int*)  d_in[0];
    const int*   llen     = (const int*)  d_in[1];
    const float* embed_w  = (const float*)d_in[2];
    const float* i2h_w    = (const float*)d_in[3];
    const float* i2h_b    = (const float*)d_in[4];
    const float* h2h_w    = (const float*)d_in[5];
    const float* h2h_b    = (const float*)d_in[6];
    const float* lin0_w   = (const float*)d_in[7];
    const float* lin0_b   = (const float*)d_in[8];
    const float* bn0_g    = (const float*)d_in[9];
    const float* bn0_b    = (const float*)d_in[10];
    const float* lin1_w   = (const float*)d_in[11];
    const float* lin1_b   = (const float*)d_in[12];
    const float* bn1_g    = (const float*)d_in[13];
    const float* bn1_b    = (const float*)d_in[14];
    float*       out      = (float*)d_out;

    const int smem_lstm = (20 * HH + 16 * BB * 4) * (int)sizeof(float);  // 72 KB
    static int attr_done = 0;
    if (!attr_done) {
        cudaFuncSetAttribute(k_lstm, cudaFuncAttributeMaxDynamicSharedMemorySize,
                             smem_lstm);
        attr_done = 1;
    }

    k_init<<<256, 256>>>(llen);
    k_pre<<<dim3(G5 / 128, (TT * BB) / 128), 256>>>(label, embed_w, i2h_w, i2h_b);
    k_lstm<<<NBLK, 256, smem_lstm>>>(h2h_w, h2h_b);
    k_head<<<LEE, BB>>>(lin0_w, lin0_b, bn0_g, bn0_b, out, 0);
    k_head<<<LEE, BB>>>(lin1_w, lin1_b, bn1_g, bn1_b, out, 1);
}